// round 8
// baseline (speedup 1.0000x reference)
#include <cuda_runtime.h>

#define FULL 0xFFFFFFFFu
typedef unsigned long long u64;

// Per-block partials + completion counter (static device scratch).
__device__ float g_partials[512];
__device__ unsigned int g_cnt = 0;

// ---- f32x2 packed helpers (sm_100+ PTX) ----
__device__ __forceinline__ u64 pk(float lo, float hi) {
    u64 d; asm("mov.b64 %0, {%1, %2};" : "=l"(d) : "f"(lo), "f"(hi)); return d;
}
__device__ __forceinline__ float lo2(u64 d) { return __uint_as_float((unsigned)d); }
__device__ __forceinline__ float hi2(u64 d) { return __uint_as_float((unsigned)(d >> 32)); }
__device__ __forceinline__ u64 fma2(u64 a, u64 b, u64 c) {
    u64 d; asm("fma.rn.f32x2 %0, %1, %2, %3;" : "=l"(d) : "l"(a), "l"(b), "l"(c)); return d;
}
__device__ __forceinline__ u64 mul2(u64 a, u64 b) {
    u64 d; asm("mul.rn.f32x2 %0, %1, %2;" : "=l"(d) : "l"(a), "l"(b)); return d;
}
__device__ __forceinline__ u64 add2(u64 a, u64 b) {
    u64 d; asm("add.rn.f32x2 %0, %1, %2;" : "=l"(d) : "l"(a), "l"(b)); return d;
}

// Two batch elements per warp (16-lane segments), 4 states/lane in f32x2 pairs.
// Linear-space scaled forward; D-chain via constant prefix products folded into
// consumers. Single FUSED 16-wide additive scan per step: scan input carries
// both z = u1+u2+u3 (lane-local) and y (the shfl-dependent u0 term rewritten
// lane-locally: u0[sl+1] = y[sl] = (cc0[sl+1]*evx[sl+1])*p3[sl]);
//   Tfull[sl] = scanIncl(z+y)[sl] - y[sl].
// All coeff*emission products pre-baked into LUTs (depend only on symbol x).
__global__ void __launch_bounds__(128)
phmm_kernel(const int* __restrict__ xin,       // (B,128) int32 in [0,4)
            const float* __restrict__ trans,   // (B,65,7)
            const float* __restrict__ emis,    // (B,64,4)
            const float* __restrict__ mus,     // (B,16)
            const float* __restrict__ logvars, // (B,16)
            float* __restrict__ out)           // scalar
{
    const int lane = threadIdx.x & 31;
    const int sl   = lane & 15;            // lane within segment
    const int seg  = lane >> 4;            // which batch of this warp
    const int warp = threadIdx.x >> 5;
    const int b = blockIdx.x * 8 + warp * 2 + seg;

    __shared__ float4 sE4[4 * 4 * 32];     // [warp][sym][lane] emission quads
    __shared__ float4 sZY[4 * 4 * 32];     // (zc1, zc2, zc3, ykc) pre-baked
    __shared__ float  sEC[4 * 4 * 32];     // e[63] replicated
    __shared__ int    sx[8 * 132];         // symbols, stride de-conflicts
    __shared__ float  sred[8];
    __shared__ int    sflag;
    __shared__ float  s2[128];

    int* sxw = &sx[(warp * 2 + seg) * 132];
    {
        const int* xb = xin + b * 128;
        #pragma unroll
        for (int i = 0; i < 8; i++) sxw[sl + 16 * i] = xb[sl + 16 * i];
    }

    // ---- transitions (order M2M,M2I,M2D,I2M,I2I,D2M,D2D), rows 4sl..4sl+3 ----
    const float* ab = trans + b * 455;
    const float* a0 = ab + 28 * sl;
    float tM2M[4], tqM2I[4], tI2M[4], tqI2I[4], tM2D[4], tD2M[4], tD2D[4];
    #pragma unroll
    for (int j = 0; j < 4; j++) {
        tM2M[j]  = __expf(a0[7 * j + 0]);
        tqM2I[j] = 0.25f * __expf(a0[7 * j + 1]);   // LOG_Q folded
        tM2D[j]  = __expf(a0[7 * j + 2]);
        tI2M[j]  = __expf(a0[7 * j + 3]);
        tqI2I[j] = 0.25f * __expf(a0[7 * j + 4]);
        tD2M[j]  = __expf(a0[7 * j + 5]);
        tD2D[j]  = __expf(a0[7 * j + 6]);
    }
    const float* a64 = ab + 64 * 7;
    float t64M2M  = __expf(a64[0]);
    float tq64M2I = 0.25f * __expf(a64[1]);
    float t64I2M  = __expf(a64[3]);
    float tq64I2I = 0.25f * __expf(a64[4]);
    float t64D2M  = __expf(a64[5]);

    // ---- prefix products of D-chain coefficients (constant in time) ----
    float P64fac, cc0v, cc1v, cc2v, cc3v, ccn;
    u64 dd01, dd23;
    {
        float q0 = tD2D[0], q01 = q0 * tD2D[1], q012 = q01 * tD2D[2], q0123 = q012 * tD2D[3];
        float Q = q0123;
        #pragma unroll
        for (int off = 1; off < 16; off <<= 1) {
            float q = __shfl_up_sync(FULL, Q, off, 16);
            if (sl >= off) Q *= q;
        }
        float Pex = __shfl_up_sync(FULL, Q, 1, 16);   // P[4sl]
        if (sl == 0) Pex = 1.0f;
        float Pa = Pex * q0, Pb = Pex * q01, Pc = Pex * q012, Pd = Pex * q0123;
        dd01 = pk(tD2M[0] * Pex, tD2M[1] * Pa);
        dd23 = pk(tD2M[2] * Pb,  tD2M[3] * Pc);
        cc0v = __fdividef(tM2D[0], Pa);
        cc1v = __fdividef(tM2D[1], Pb);
        cc2v = __fdividef(tM2D[2], Pc);
        cc3v = __fdividef(tM2D[3], Pd);
        ccn = __shfl_down_sync(FULL, cc0v, 1, 16);    // cc0 of next lane
        if (sl == 15) ccn = 0.0f;
        P64fac = Pd;                        // on sl=15: P[64]
    }

    // ---- emission + pre-baked coefficient LUTs ----
    const float* eb = emis + b * 256;
    {
        #pragma unroll
        for (int x = 0; x < 4; x++) {
            float4 v;
            v.x = (sl == 0) ? 0.0f : __expf(eb[(4 * sl - 1) * 4 + x]);
            v.y = __expf(eb[(4 * sl + 0) * 4 + x]);
            v.z = __expf(eb[(4 * sl + 1) * 4 + x]);
            v.w = __expf(eb[(4 * sl + 2) * 4 + x]);
            sE4[(warp * 4 + x) * 32 + lane] = v;
            sEC[(warp * 4 + x) * 32 + lane] = __expf(eb[63 * 4 + x]);
            // next lane's ev.x = e[4sl+3]; sl=15 unused (ccn=0)
            float evx = (sl == 15) ? 0.0f : __expf(eb[(4 * sl + 3) * 4 + x]);
            float4 zy;
            zy.x = cc1v * v.y;     // u1 = zy.x * p0
            zy.y = cc2v * v.z;     // u2 = zy.y * p1
            zy.z = cc3v * v.w;     // u3 = zy.z * p2
            zy.w = ccn * evx;      // y  = zy.w * p3
            sZY[(warp * 4 + x) * 32 + lane] = zy;
        }
    }
    __syncwarp();

    const u64 tM2M01  = pk(tM2M[0], tM2M[1]),   tM2M23  = pk(tM2M[2], tM2M[3]);
    const u64 tI2M01  = pk(tI2M[0], tI2M[1]),   tI2M23  = pk(tI2M[2], tI2M[3]);
    const u64 tqI2I01 = pk(tqI2I[0], tqI2I[1]), tqI2I23 = pk(tqI2I[2], tqI2I[3]);
    const u64 tqM2I01 = pk(tqM2I[0], tqM2I[1]), tqM2I23 = pk(tqM2I[2], tqM2I[3]);

    // ---- init states ----
    u64 FM01 = pk((sl == 0) ? 1.0f : 0.0f, 0.0f), FM23 = pk(0.0f, 0.0f);
    u64 FI01 = pk(0.0f, 0.0f), FI23 = pk(0.0f, 0.0f);
    float FM64 = 0.0f, FI64 = 0.0f;
    u64 w01, w23, PRE01, PRE23;
    float incl, S = 0.0f;

    unsigned sE4a = (unsigned)__cvta_generic_to_shared(&sE4[warp * 128 + lane]);
    unsigned sZYa = (unsigned)__cvta_generic_to_shared(&sZY[warp * 128 + lane]);
    const float* sECw = &sEC[warp * 128 + lane];

    // initial D-chain (plain scan) + PRE
    {
        float u0 = cc0v * lo2(FM01), u1 = cc1v * hi2(FM01);
        float u2 = cc2v * lo2(FM23), u3 = cc3v * hi2(FM23);
        float s0 = u0, s1 = s0 + u1, s2 = s1 + u2, s3 = s2 + u3;
        float T = s3;
        #pragma unroll
        for (int off = 1; off < 16; off <<= 1) {
            float t = __shfl_up_sync(FULL, T, off, 16);
            if (sl >= off) T += t;
        }
        incl = T;
        float ex = T - s3;
        w01 = pk(ex, ex + s0);
        w23 = pk(ex + s1, ex + s2);
        PRE01 = fma2(tI2M01, FI01, mul2(tM2M01, FM01));
        PRE23 = fma2(tI2M23, FI23, mul2(tM2M23, FM23));
    }

#define STEP(x)                                                               \
    {                                                                         \
        u64 ev01, ev23, zy01, zy23;                                           \
        asm("ld.shared.v2.u64 {%0, %1}, [%2];"                                \
            : "=l"(ev01), "=l"(ev23) : "r"(sE4a + (unsigned)(x) * 512));      \
        asm("ld.shared.v2.u64 {%0, %1}, [%2];"                                \
            : "=l"(zy01), "=l"(zy23) : "r"(sZYa + (unsigned)(x) * 512));      \
        float eC = sECw[(x) * 32];                                            \
        u64 p01 = fma2(dd01, w01, PRE01);                                     \
        u64 p23 = fma2(dd23, w23, PRE23);                                     \
        float p0 = lo2(p01), p1 = hi2(p01), p2 = lo2(p23), p3 = hi2(p23);     \
        u64 m1 = mul2(zy01, p01);        /* (u1, u2) */                       \
        u64 m2 = mul2(zy23, p23);        /* (u3, y)  */                       \
        u64 hh = add2(m1, m2);           /* (u1+u3, u2+y) */                  \
        float scanin = lo2(hh) + hi2(hh);                                     \
        float y = hi2(m2);                                                    \
        float T = scanin;                                                     \
        _Pragma("unroll")                                                     \
        for (int off = 1; off < 16; off <<= 1) {                              \
            float t = __shfl_up_sync(FULL, T, off, 16);                       \
            if (sl >= off) T += t;                                            \
        }                                                                     \
        float pUp = __shfl_up_sync(FULL, p3, 1, 16);   /* runs with scan */   \
        float FM0 = lo2(ev01) * pUp;     /* sl0: ev.x==0 -> 0 */              \
        float u0  = cc0v * FM0;                                               \
        FI01 = fma2(tqI2I01, FI01, mul2(tqM2I01, FM01));  /* OLD FM */        \
        FI23 = fma2(tqI2I23, FI23, mul2(tqM2I23, FM23));                      \
        FI64 = fmaf(tq64I2I, FI64, tq64M2I * FM64);                           \
        FM01 = mul2(ev01, pk(pUp, p0));                                       \
        FM23 = mul2(ev23, pk(p1, p2));                                        \
        FM64 = eC * p3;                  /* valid on sl=15 */                 \
        float Tfull = T - y;                                                  \
        incl = Tfull;                                                         \
        float z = scanin - y;            /* u1+u2+u3 */                       \
        float w0 = Tfull - (u0 + z);                                          \
        float w1 = w0 + u0;                                                   \
        float w2 = w1 + lo2(m1);         /* +u1 */                            \
        float w3 = w2 + hi2(m1);         /* +u2 */                            \
        w01 = pk(w0, w1); w23 = pk(w2, w3);                                   \
        PRE01 = fma2(tI2M01, FI01, mul2(tM2M01, FM01));  /* off-path */       \
        PRE23 = fma2(tI2M23, FI23, mul2(tM2M23, FM23));                       \
    }

    #pragma unroll 1
    for (int lq = 0; lq < 16; lq++) {
        int4 xa = *(const int4*)&sxw[8 * lq];
        int4 xb4 = *(const int4*)&sxw[8 * lq + 4];
        STEP(xa.x); STEP(xa.y); STEP(xa.z); STEP(xa.w);
        STEP(xb4.x); STEP(xb4.y); STEP(xb4.z); STEP(xb4.w);
        // rescale by segment max
        float m = fmaxf(fmaxf(lo2(FM01), hi2(FM01)), fmaxf(lo2(FM23), hi2(FM23)));
        m = fmaxf(m, fmaxf(fmaxf(lo2(FI01), hi2(FI01)), fmaxf(lo2(FI23), hi2(FI23))));
        m = fmaxf(m, fmaxf(FM64, FI64));
        #pragma unroll
        for (int off = 1; off < 16; off <<= 1)
            m = fmaxf(m, __shfl_xor_sync(FULL, m, off, 16));
        m = fmaxf(m, 1e-30f);
        float r = 1.0f / m;
        S += __logf(m);
        u64 rr = pk(r, r);
        FM01 = mul2(FM01, rr); FM23 = mul2(FM23, rr);
        FI01 = mul2(FI01, rr); FI23 = mul2(FI23, rr);
        w01 = mul2(w01, rr);   w23 = mul2(w23, rr);
        PRE01 = mul2(PRE01, rr); PRE23 = mul2(PRE23, rr);  // linear in states
        FM64 *= r; FI64 *= r; incl *= r;
    }

    // ---- final: three end transitions (sl=15 holds state 64 & full prefix) ----
    float fdTop = P64fac * incl;
    float Pfin = fmaf(t64D2M, fdTop, fmaf(t64I2M, FI64, t64M2M * FM64));
    float loss = -(S + __logf(Pfin));             // valid on sl=15

    // ---- KLD: 16 segment lanes, one latent dim each ----
    float kt;
    {
        float mu = mus[b * 16 + sl];
        float lv = logvars[b * 16 + sl];
        kt = 1.0f + lv - mu * mu - __expf(lv);
    }
    #pragma unroll
    for (int off = 1; off < 16; off <<= 1)
        kt += __shfl_xor_sync(FULL, kt, off, 16);

    if (sl == 15) sred[warp * 2 + seg] = loss - 0.5f * kt;
    __syncthreads();
    if (threadIdx.x == 0) {
        float v = ((sred[0] + sred[1]) + (sred[2] + sred[3]))
                + ((sred[4] + sred[5]) + (sred[6] + sred[7]));
        g_partials[blockIdx.x] = v;
        __threadfence();
        unsigned t = atomicAdd(&g_cnt, 1u);
        sflag = (t == gridDim.x - 1) ? 1 : 0;
    }
    __syncthreads();
    if (sflag) {
        float s = 0.0f;
        #pragma unroll
        for (int i = 0; i < 4; i++)
            s += __ldcg(&g_partials[threadIdx.x + 128 * i]);
        s2[threadIdx.x] = s;
        __syncthreads();
        #pragma unroll
        for (int st = 64; st; st >>= 1) {
            if (threadIdx.x < st) s2[threadIdx.x] += s2[threadIdx.x + st];
            __syncthreads();
        }
        if (threadIdx.x == 0) {
            out[0] = s2[0] * (1.0f / 4096.0f);
            g_cnt = 0;  // self-reset for graph replay
        }
    }
#undef STEP
}

extern "C" void kernel_launch(void* const* d_in, const int* in_sizes, int n_in,
                              void* d_out, int out_size) {
    const int*   x  = (const int*)d_in[0];    // batch_input (B,128)
    const float* a  = (const float*)d_in[1];  // transition_probs (B,65,7)
    const float* e  = (const float*)d_in[2];  // emission_probs (B,64,4)
    const float* mu = (const float*)d_in[3];  // mus (B,16)
    const float* lv = (const float*)d_in[4];  // logvars (B,16)
    const int B = in_sizes[0] / 128;          // 4096
    phmm_kernel<<<B / 8, 128>>>(x, a, e, mu, lv, (float*)d_out);
}

// round 11
// speedup vs baseline: 1.0534x; 1.0534x over previous
#include <cuda_runtime.h>

#define FULL 0xFFFFFFFFu
typedef unsigned long long u64;

// Per-block partials + completion counter (static device scratch).
__device__ float g_partials[256];
__device__ unsigned int g_cnt = 0;

// ---- f32x2 packed helpers (sm_100+ PTX) ----
__device__ __forceinline__ u64 pk(float lo, float hi) {
    u64 d; asm("mov.b64 %0, {%1, %2};" : "=l"(d) : "f"(lo), "f"(hi)); return d;
}
__device__ __forceinline__ float lo2(u64 d) { return __uint_as_float((unsigned)d); }
__device__ __forceinline__ float hi2(u64 d) { return __uint_as_float((unsigned)(d >> 32)); }
__device__ __forceinline__ u64 fma2(u64 a, u64 b, u64 c) {
    u64 d; asm("fma.rn.f32x2 %0, %1, %2, %3;" : "=l"(d) : "l"(a), "l"(b), "l"(c)); return d;
}
__device__ __forceinline__ u64 mul2(u64 a, u64 b) {
    u64 d; asm("mul.rn.f32x2 %0, %1, %2;" : "=l"(d) : "l"(a), "l"(b)); return d;
}
__device__ __forceinline__ u64 add2(u64 a, u64 b) {
    u64 d; asm("add.rn.f32x2 %0, %1, %2;" : "=l"(d) : "l"(a), "l"(b)); return d;
}

// FOUR batch elements per warp (8-lane segments), 8 states/lane in 4 f32x2
// pairs. Linear-space scaled forward; D-chain via constant prefix products
// folded into consumers; 8-wide segmented additive scan (3 shfl stages),
// all-additive w reconstruction (no y-trick, no suffix subtraction).
__global__ void __launch_bounds__(128)
phmm_kernel(const int* __restrict__ xin,       // (B,128) int32 in [0,4)
            const float* __restrict__ trans,   // (B,65,7)
            const float* __restrict__ emis,    // (B,64,4)
            const float* __restrict__ mus,     // (B,16)
            const float* __restrict__ logvars, // (B,16)
            float* __restrict__ out)           // scalar
{
    const int lane = threadIdx.x & 31;
    const int sl   = lane & 7;             // lane within 8-wide segment
    const int seg  = lane >> 3;            // which batch of this warp (0..3)
    const int warp = threadIdx.x >> 5;
    const int b = blockIdx.x * 16 + warp * 4 + seg;

    // LUTs indexed [(warp*4+sym)*32 + lane]
    __shared__ float4 sEa[512], sEb[512];  // emissions e[8sl-1 .. 8sl+6]
    __shared__ float  sEC[512];            // e[63]
    __shared__ int    sx[16 * 132];
    __shared__ float  sred[16];
    __shared__ int    sflag;
    __shared__ float  s2[128];

    int* sxw = &sx[(warp * 4 + seg) * 132];
    {
        const int* xb = xin + b * 128;
        #pragma unroll
        for (int i = 0; i < 16; i++) sxw[sl + 8 * i] = xb[sl + 8 * i];
    }

    // ---- transitions (order M2M,M2I,M2D,I2M,I2I,D2M,D2D), rows 8sl..8sl+7 ----
    const float* ab = trans + b * 455;
    const float* a0 = ab + 56 * sl;
    float tM2M[8], tqM2I[8], tI2M[8], tqI2I[8], tM2D[8], tD2M[8], tD2D[8];
    #pragma unroll
    for (int j = 0; j < 8; j++) {
        tM2M[j]  = __expf(a0[7 * j + 0]);
        tqM2I[j] = 0.25f * __expf(a0[7 * j + 1]);   // LOG_Q folded
        tM2D[j]  = __expf(a0[7 * j + 2]);
        tI2M[j]  = __expf(a0[7 * j + 3]);
        tqI2I[j] = 0.25f * __expf(a0[7 * j + 4]);
        tD2M[j]  = __expf(a0[7 * j + 5]);
        tD2D[j]  = __expf(a0[7 * j + 6]);
    }
    const float* a64 = ab + 64 * 7;
    float t64M2M  = __expf(a64[0]);
    float tq64M2I = 0.25f * __expf(a64[1]);
    float t64I2M  = __expf(a64[3]);
    float tq64I2I = 0.25f * __expf(a64[4]);
    float t64D2M  = __expf(a64[5]);

    // ---- prefix products of D-chain coefficients ----
    // P[k] = prod_{i<k} tD2D[i]; cc_j = tM2D[j]/P[8sl+j+1]; dd_j = tD2M[j]*P[8sl+j].
    float P64fac;
    u64 cc01, cc23, cc45, cc67, dd01, dd23, dd45, dd67;
    {
        float r[9];
        r[0] = 1.0f;
        #pragma unroll
        for (int j = 0; j < 8; j++) r[j + 1] = r[j] * tD2D[j];
        float Q = r[8];
        #pragma unroll
        for (int off = 1; off < 8; off <<= 1) {
            float q = __shfl_up_sync(FULL, Q, off, 8);
            if (sl >= off) Q *= q;
        }
        P64fac = Q;                                   // sl=7: P[64]
        float Pex = __shfl_up_sync(FULL, Q, 1, 8);    // P[8sl]
        if (sl == 0) Pex = 1.0f;
        float cct[8];
        #pragma unroll
        for (int j = 0; j < 8; j++)
            cct[j] = __fdividef(tM2D[j], Pex * r[j + 1]);
        cc01 = pk(cct[0], cct[1]); cc23 = pk(cct[2], cct[3]);
        cc45 = pk(cct[4], cct[5]); cc67 = pk(cct[6], cct[7]);
        dd01 = pk(tD2M[0] * Pex,        tD2M[1] * Pex * r[1]);
        dd23 = pk(tD2M[2] * Pex * r[2], tD2M[3] * Pex * r[3]);
        dd45 = pk(tD2M[4] * Pex * r[4], tD2M[5] * Pex * r[5]);
        dd67 = pk(tD2M[6] * Pex * r[6], tD2M[7] * Pex * r[7]);
    }

    // ---- emission LUTs ----
    const float* eb = emis + b * 256;
    {
        #pragma unroll
        for (int x = 0; x < 4; x++) {
            float ev[8];
            ev[0] = (sl == 0) ? 0.0f : __expf(eb[(8 * sl - 1) * 4 + x]);
            #pragma unroll
            for (int j = 1; j < 8; j++)
                ev[j] = __expf(eb[(8 * sl + j - 1) * 4 + x]);
            int idx = (warp * 4 + x) * 32 + lane;
            sEa[idx] = make_float4(ev[0], ev[1], ev[2], ev[3]);
            sEb[idx] = make_float4(ev[4], ev[5], ev[6], ev[7]);
            sEC[idx] = __expf(eb[63 * 4 + x]);
        }
    }
    __syncwarp();

    const u64 tM2M01  = pk(tM2M[0], tM2M[1]),   tM2M23  = pk(tM2M[2], tM2M[3]);
    const u64 tM2M45  = pk(tM2M[4], tM2M[5]),   tM2M67  = pk(tM2M[6], tM2M[7]);
    const u64 tI2M01  = pk(tI2M[0], tI2M[1]),   tI2M23  = pk(tI2M[2], tI2M[3]);
    const u64 tI2M45  = pk(tI2M[4], tI2M[5]),   tI2M67  = pk(tI2M[6], tI2M[7]);
    const u64 tqI2I01 = pk(tqI2I[0], tqI2I[1]), tqI2I23 = pk(tqI2I[2], tqI2I[3]);
    const u64 tqI2I45 = pk(tqI2I[4], tqI2I[5]), tqI2I67 = pk(tqI2I[6], tqI2I[7]);
    const u64 tqM2I01 = pk(tqM2I[0], tqM2I[1]), tqM2I23 = pk(tqM2I[2], tqM2I[3]);
    const u64 tqM2I45 = pk(tqM2I[4], tqM2I[5]), tqM2I67 = pk(tqM2I[6], tqM2I[7]);

    // ---- init states ----
    u64 FM01 = pk((sl == 0) ? 1.0f : 0.0f, 0.0f);
    u64 FM23 = pk(0.0f, 0.0f), FM45 = pk(0.0f, 0.0f), FM67 = pk(0.0f, 0.0f);
    u64 FI01 = pk(0.0f, 0.0f), FI23 = pk(0.0f, 0.0f);
    u64 FI45 = pk(0.0f, 0.0f), FI67 = pk(0.0f, 0.0f);
    float FM64 = 0.0f, FI64 = 0.0f;
    u64 w01, w23, w45, w67, PRE01, PRE23, PRE45, PRE67;
    float incl, S = 0.0f;

    const float4* sEaw = &sEa[warp * 128 + lane];
    const float4* sEbw = &sEb[warp * 128 + lane];
    const float*  sECw = &sEC[warp * 128 + lane];

    // D-chain scan + w reconstruction from current FM (all-additive).
#define DCHAIN()                                                              \
    {                                                                         \
        u64 u01 = mul2(cc01, FM01), u23 = mul2(cc23, FM23);                   \
        u64 u45 = mul2(cc45, FM45), u67 = mul2(cc67, FM67);                   \
        u64 uu = add2(add2(u01, u23), add2(u45, u67));                        \
        float s7 = lo2(uu) + hi2(uu);                                         \
        float T = s7;                                                         \
        _Pragma("unroll")                                                     \
        for (int off = 1; off < 8; off <<= 1) {                               \
            float t = __shfl_up_sync(FULL, T, off, 8);                        \
            if (sl >= off) T += t;                                            \
        }                                                                     \
        /* off-path: local serial prefixes */                                 \
        float u0 = lo2(u01), u1 = hi2(u01), u2 = lo2(u23), u3 = hi2(u23);     \
        float u4 = lo2(u45), u5 = hi2(u45), u6 = lo2(u67);                    \
        float s0 = u0, s1 = s0 + u1, s2 = s1 + u2, s3 = s2 + u3;              \
        float s4 = s3 + u4, s5 = s4 + u5, s6 = s5 + u6;                       \
        float ex = T - s7;                                                    \
        incl = T;                                                             \
        w01 = pk(ex, ex + s0);                                                \
        w23 = pk(ex + s1, ex + s2);                                           \
        w45 = pk(ex + s3, ex + s4);                                           \
        w67 = pk(ex + s5, ex + s6);                                           \
    }

#define STEP(XS)                                                              \
    {                                                                         \
        float4 eA = sEaw[(XS) * 32];                                          \
        float4 eB = sEbw[(XS) * 32];                                          \
        float  eC = sECw[(XS) * 32];                                          \
        u64 p01 = fma2(dd01, w01, PRE01);                                     \
        u64 p23 = fma2(dd23, w23, PRE23);                                     \
        u64 p45 = fma2(dd45, w45, PRE45);                                     \
        u64 p67 = fma2(dd67, w67, PRE67);                                     \
        float p7 = hi2(p67);                                                  \
        float pUp = __shfl_up_sync(FULL, p7, 1, 8);                           \
        FI01 = fma2(tqI2I01, FI01, mul2(tqM2I01, FM01));  /* OLD FM */        \
        FI23 = fma2(tqI2I23, FI23, mul2(tqM2I23, FM23));                      \
        FI45 = fma2(tqI2I45, FI45, mul2(tqM2I45, FM45));                      \
        FI67 = fma2(tqI2I67, FI67, mul2(tqM2I67, FM67));                      \
        FI64 = fmaf(tq64I2I, FI64, tq64M2I * FM64);                           \
        FM01 = mul2(pk(eA.x, eA.y), pk(pUp, lo2(p01)));  /* sl0: eA.x==0 */   \
        FM23 = mul2(pk(eA.z, eA.w), pk(hi2(p01), lo2(p23)));                  \
        FM45 = mul2(pk(eB.x, eB.y), pk(hi2(p23), lo2(p45)));                  \
        FM67 = mul2(pk(eB.z, eB.w), pk(hi2(p45), lo2(p67)));                  \
        FM64 = eC * p7;                    /* valid on sl=7 */                \
        DCHAIN();                                                             \
        PRE01 = fma2(tI2M01, FI01, mul2(tM2M01, FM01));                       \
        PRE23 = fma2(tI2M23, FI23, mul2(tM2M23, FM23));                       \
        PRE45 = fma2(tI2M45, FI45, mul2(tM2M45, FM45));                       \
        PRE67 = fma2(tI2M67, FI67, mul2(tM2M67, FM67));                       \
    }

    DCHAIN();   // from initial fM
    PRE01 = fma2(tI2M01, FI01, mul2(tM2M01, FM01));
    PRE23 = fma2(tI2M23, FI23, mul2(tM2M23, FM23));
    PRE45 = fma2(tI2M45, FI45, mul2(tM2M45, FM45));
    PRE67 = fma2(tI2M67, FI67, mul2(tM2M67, FM67));

    #pragma unroll 1
    for (int lq = 0; lq < 16; lq++) {
        int4 xa = *(const int4*)&sxw[8 * lq];
        int4 xb4 = *(const int4*)&sxw[8 * lq + 4];
        STEP(xa.x); STEP(xa.y); STEP(xa.z); STEP(xa.w);
        STEP(xb4.x); STEP(xb4.y); STEP(xb4.z); STEP(xb4.w);
        // rescale by segment max
        float m = fmaxf(fmaxf(lo2(FM01), hi2(FM01)), fmaxf(lo2(FM23), hi2(FM23)));
        m = fmaxf(m, fmaxf(fmaxf(lo2(FM45), hi2(FM45)), fmaxf(lo2(FM67), hi2(FM67))));
        m = fmaxf(m, fmaxf(fmaxf(lo2(FI01), hi2(FI01)), fmaxf(lo2(FI23), hi2(FI23))));
        m = fmaxf(m, fmaxf(fmaxf(lo2(FI45), hi2(FI45)), fmaxf(lo2(FI67), hi2(FI67))));
        m = fmaxf(m, fmaxf(FM64, FI64));
        #pragma unroll
        for (int off = 1; off < 8; off <<= 1)
            m = fmaxf(m, __shfl_xor_sync(FULL, m, off, 8));
        m = fmaxf(m, 1e-30f);
        float r = 1.0f / m;
        S += __logf(m);
        u64 rr = pk(r, r);
        FM01 = mul2(FM01, rr); FM23 = mul2(FM23, rr);
        FM45 = mul2(FM45, rr); FM67 = mul2(FM67, rr);
        FI01 = mul2(FI01, rr); FI23 = mul2(FI23, rr);
        FI45 = mul2(FI45, rr); FI67 = mul2(FI67, rr);
        w01 = mul2(w01, rr);   w23 = mul2(w23, rr);
        w45 = mul2(w45, rr);   w67 = mul2(w67, rr);
        PRE01 = mul2(PRE01, rr); PRE23 = mul2(PRE23, rr);
        PRE45 = mul2(PRE45, rr); PRE67 = mul2(PRE67, rr);
        FM64 *= r; FI64 *= r; incl *= r;
    }

    // ---- final: three end transitions (sl=7 holds state 64 & full prefix) ----
    float fdTop = P64fac * incl;
    float Pfin = fmaf(t64D2M, fdTop, fmaf(t64I2M, FI64, t64M2M * FM64));
    float loss = -(S + __logf(Pfin));             // valid on sl=7

    // ---- KLD: 8 segment lanes, two latent dims each ----
    float kt;
    {
        float mu0 = mus[b * 16 + sl],     lv0 = logvars[b * 16 + sl];
        float mu1 = mus[b * 16 + sl + 8], lv1 = logvars[b * 16 + sl + 8];
        kt = (1.0f + lv0 - mu0 * mu0 - __expf(lv0))
           + (1.0f + lv1 - mu1 * mu1 - __expf(lv1));
    }
    #pragma unroll
    for (int off = 1; off < 8; off <<= 1)
        kt += __shfl_xor_sync(FULL, kt, off, 8);

    if (sl == 7) sred[warp * 4 + seg] = loss - 0.5f * kt;
    __syncthreads();
    if (threadIdx.x == 0) {
        float v = 0.0f;
        #pragma unroll
        for (int i = 0; i < 16; i++) v += sred[i];
        g_partials[blockIdx.x] = v;
        __threadfence();
        unsigned t = atomicAdd(&g_cnt, 1u);
        sflag = (t == gridDim.x - 1) ? 1 : 0;
    }
    __syncthreads();
    if (sflag) {
        float s = __ldcg(&g_partials[threadIdx.x])
                + __ldcg(&g_partials[threadIdx.x + 128]);
        s2[threadIdx.x] = s;
        __syncthreads();
        #pragma unroll
        for (int st = 64; st; st >>= 1) {
            if (threadIdx.x < st) s2[threadIdx.x] += s2[threadIdx.x + st];
            __syncthreads();
        }
        if (threadIdx.x == 0) {
            out[0] = s2[0] * (1.0f / 4096.0f);
            g_cnt = 0;  // self-reset for graph replay
        }
    }
#undef STEP
#undef DCHAIN
}

extern "C" void kernel_launch(void* const* d_in, const int* in_sizes, int n_in,
                              void* d_out, int out_size) {
    const int*   x  = (const int*)d_in[0];    // batch_input (B,128)
    const float* a  = (const float*)d_in[1];  // transition_probs (B,65,7)
    const float* e  = (const float*)d_in[2];  // emission_probs (B,64,4)
    const float* mu = (const float*)d_in[3];  // mus (B,16)
    const float* lv = (const float*)d_in[4];  // logvars (B,16)
    const int B = in_sizes[0] / 128;          // 4096
    phmm_kernel<<<B / 16, 128>>>(x, a, e, mu, lv, (float*)d_out);
}

// round 12
// speedup vs baseline: 1.0615x; 1.0077x over previous
#include <cuda_runtime.h>

#define FULL 0xFFFFFFFFu
typedef unsigned long long u64;

// Per-block partials + completion counter (static device scratch).
__device__ float g_partials[512];
__device__ unsigned int g_cnt = 0;

// ---- f32x2 packed helpers (sm_100+ PTX) ----
__device__ __forceinline__ u64 pk(float lo, float hi) {
    u64 d; asm("mov.b64 %0, {%1, %2};" : "=l"(d) : "f"(lo), "f"(hi)); return d;
}
__device__ __forceinline__ float lo2(u64 d) { return __uint_as_float((unsigned)d); }
__device__ __forceinline__ float hi2(u64 d) { return __uint_as_float((unsigned)(d >> 32)); }
__device__ __forceinline__ u64 fma2(u64 a, u64 b, u64 c) {
    u64 d; asm("fma.rn.f32x2 %0, %1, %2, %3;" : "=l"(d) : "l"(a), "l"(b), "l"(c)); return d;
}
__device__ __forceinline__ u64 mul2(u64 a, u64 b) {
    u64 d; asm("mul.rn.f32x2 %0, %1, %2;" : "=l"(d) : "l"(a), "l"(b)); return d;
}

// Two batch elements per warp (16-lane segments), 4 states/lane in f32x2 pairs.
// Linear-space scaled forward; D-chain via constant prefix products folded
// into consumers; single 16-wide segmented additive scan (4 shfl stages) with
// GUARD-FREE mask-FFMA combine (mask precomputed per lane, keeps the
// pred-as-guard penalty off the critical path).
__global__ void __launch_bounds__(128)
phmm_kernel(const int* __restrict__ xin,       // (B,128) int32 in [0,4)
            const float* __restrict__ trans,   // (B,65,7)
            const float* __restrict__ emis,    // (B,64,4)
            const float* __restrict__ mus,     // (B,16)
            const float* __restrict__ logvars, // (B,16)
            float* __restrict__ out)           // scalar
{
    const int lane = threadIdx.x & 31;
    const int sl   = lane & 15;            // lane within segment
    const int seg  = lane >> 4;            // which batch of this warp
    const int warp = threadIdx.x >> 5;
    const int b = blockIdx.x * 8 + warp * 2 + seg;

    __shared__ float4 sE4[4 * 4 * 32];     // [warp][sym][lane] emission quads
    __shared__ float  sEC[4 * 4 * 32];     // e[63] replicated
    __shared__ int    sx[8 * 132];         // symbols, stride de-conflicts
    __shared__ float  sred[8];
    __shared__ int    sflag;
    __shared__ float  s2[128];

    int* sxw = &sx[(warp * 2 + seg) * 132];
    {
        const int* xb = xin + b * 128;
        #pragma unroll
        for (int i = 0; i < 8; i++) sxw[sl + 16 * i] = xb[sl + 16 * i];
    }

    // ---- transitions (order M2M,M2I,M2D,I2M,I2I,D2M,D2D), rows 4sl..4sl+3 ----
    const float* ab = trans + b * 455;
    const float* a0 = ab + 28 * sl;
    float tM2M[4], tqM2I[4], tI2M[4], tqI2I[4], tM2D[4], tD2M[4], tD2D[4];
    #pragma unroll
    for (int j = 0; j < 4; j++) {
        tM2M[j]  = __expf(a0[7 * j + 0]);
        tqM2I[j] = 0.25f * __expf(a0[7 * j + 1]);   // LOG_Q folded
        tM2D[j]  = __expf(a0[7 * j + 2]);
        tI2M[j]  = __expf(a0[7 * j + 3]);
        tqI2I[j] = 0.25f * __expf(a0[7 * j + 4]);
        tD2M[j]  = __expf(a0[7 * j + 5]);
        tD2D[j]  = __expf(a0[7 * j + 6]);
    }
    const float* a64 = ab + 64 * 7;
    float t64M2M  = __expf(a64[0]);
    float tq64M2I = 0.25f * __expf(a64[1]);
    float t64I2M  = __expf(a64[3]);
    float tq64I2I = 0.25f * __expf(a64[4]);
    float t64D2M  = __expf(a64[5]);

    // ---- emission LUTs ----
    const float* eb = emis + b * 256;
    {
        #pragma unroll
        for (int x = 0; x < 4; x++) {
            float4 v;
            v.x = (sl == 0) ? 0.0f : __expf(eb[(4 * sl - 1) * 4 + x]);
            v.y = __expf(eb[(4 * sl + 0) * 4 + x]);
            v.z = __expf(eb[(4 * sl + 1) * 4 + x]);
            v.w = __expf(eb[(4 * sl + 2) * 4 + x]);
            sE4[(warp * 4 + x) * 32 + lane] = v;
            sEC[(warp * 4 + x) * 32 + lane] = __expf(eb[63 * 4 + x]);
        }
    }
    __syncwarp();

    // ---- prefix products of D-chain coefficients (constant in time) ----
    float P_B, cA, cB, cC, cD;
    u64 dd01, dd23;
    {
        float q0 = tD2D[0], q01 = q0 * tD2D[1], q012 = q01 * tD2D[2], q0123 = q012 * tD2D[3];
        float Q = q0123;
        #pragma unroll
        for (int off = 1; off < 16; off <<= 1) {
            float q = __shfl_up_sync(FULL, Q, off, 16);
            if (sl >= off) Q *= q;
        }
        float Pex = __shfl_up_sync(FULL, Q, 1, 16);   // P[4sl]
        if (sl == 0) Pex = 1.0f;
        float Pa = Pex * q0, Pb = Pex * q01, Pc = Pex * q012, Pd = Pex * q0123;
        dd01 = pk(tD2M[0] * Pex, tD2M[1] * Pa);
        dd23 = pk(tD2M[2] * Pb,  tD2M[3] * Pc);
        cA = __fdividef(tM2D[0], Pa);
        cB = __fdividef(tM2D[1], Pb);
        cC = __fdividef(tM2D[2], Pc);
        cD = __fdividef(tM2D[3], Pd);
        P_B = Q;                            // on sl=15: P[64]
    }
    const u64 cc01 = pk(cA, cB), cc23 = pk(cC, cD);
    const u64 tM2M01  = pk(tM2M[0], tM2M[1]),   tM2M23  = pk(tM2M[2], tM2M[3]);
    const u64 tI2M01  = pk(tI2M[0], tI2M[1]),   tI2M23  = pk(tI2M[2], tI2M[3]);
    const u64 tqI2I01 = pk(tqI2I[0], tqI2I[1]), tqI2I23 = pk(tqI2I[2], tqI2I[3]);
    const u64 tqM2I01 = pk(tqM2I[0], tqM2I[1]), tqM2I23 = pk(tqM2I[2], tqM2I[3]);

    // Guard-free scan masks: mk_i = (sl >= 2^i) ? 1 : 0
    const float mk1 = (sl >= 1) ? 1.0f : 0.0f;
    const float mk2 = (sl >= 2) ? 1.0f : 0.0f;
    const float mk4 = (sl >= 4) ? 1.0f : 0.0f;
    const float mk8 = (sl >= 8) ? 1.0f : 0.0f;

    // ---- init states ----
    u64 FM01 = pk((sl == 0) ? 1.0f : 0.0f, 0.0f), FM23 = pk(0.0f, 0.0f);
    u64 FI01 = pk(0.0f, 0.0f), FI23 = pk(0.0f, 0.0f);
    float FM64 = 0.0f, FI64 = 0.0f;
    u64 w01, w23, PRE01, PRE23;
    float incl, S = 0.0f;

    unsigned sE4a = (unsigned)__cvta_generic_to_shared(&sE4[warp * 128 + lane]);
    const float* sECw = &sEC[warp * 128 + lane];

    // D-chain: fD[k] = P[k]*prefixsum(u); scan with mask-FFMA combine.
#define DCHAIN()                                                              \
    {                                                                         \
        u64 u01 = mul2(cc01, FM01);                                           \
        u64 u23 = mul2(cc23, FM23);                                           \
        float u0 = lo2(u01), u1 = hi2(u01), u2 = lo2(u23), u3 = hi2(u23);     \
        float s0 = u0, s1 = s0 + u1, s2 = s1 + u2, s3 = s2 + u3;              \
        float T = s3;                                                         \
        float t1 = __shfl_up_sync(FULL, T, 1, 16);  T = fmaf(mk1, t1, T);     \
        float t2 = __shfl_up_sync(FULL, T, 2, 16);  T = fmaf(mk2, t2, T);     \
        float t4 = __shfl_up_sync(FULL, T, 4, 16);  T = fmaf(mk4, t4, T);     \
        float t8 = __shfl_up_sync(FULL, T, 8, 16);  T = fmaf(mk8, t8, T);     \
        incl = T;                                                             \
        float ex = T - s3;                                                    \
        w01 = pk(ex, ex + s0);                                                \
        w23 = pk(ex + s1, ex + s2);                                           \
    }

#define STEP(XS)                                                              \
    {                                                                         \
        u64 ev01, ev23;                                                       \
        asm("ld.shared.v2.u64 {%0, %1}, [%2];"                                \
            : "=l"(ev01), "=l"(ev23) : "r"(sE4a + (unsigned)(XS) * 512));     \
        float eC = sECw[(XS) * 32];                                           \
        u64 p01 = fma2(dd01, w01, PRE01);                                     \
        u64 p23 = fma2(dd23, w23, PRE23);                                     \
        float p3 = hi2(p23);                                                  \
        float pUp = __shfl_up_sync(FULL, p3, 1, 16);                          \
        FI01 = fma2(tqI2I01, FI01, mul2(tqM2I01, FM01));  /* OLD FM */        \
        FI23 = fma2(tqI2I23, FI23, mul2(tqM2I23, FM23));                      \
        FI64 = fmaf(tq64I2I, FI64, tq64M2I * FM64);                           \
        FM01 = mul2(ev01, pk(pUp, lo2(p01)));  /* sl0: ev.x==0 */             \
        FM23 = mul2(ev23, pk(hi2(p01), lo2(p23)));                            \
        FM64 = eC * p3;                        /* valid on sl=15 */           \
        DCHAIN();                                                             \
        PRE01 = fma2(tI2M01, FI01, mul2(tM2M01, FM01));                       \
        PRE23 = fma2(tI2M23, FI23, mul2(tM2M23, FM23));                       \
    }

    DCHAIN();   // from initial fM
    PRE01 = fma2(tI2M01, FI01, mul2(tM2M01, FM01));
    PRE23 = fma2(tI2M23, FI23, mul2(tM2M23, FM23));

    #pragma unroll 1
    for (int lq = 0; lq < 16; lq++) {
        int4 xa = *(const int4*)&sxw[8 * lq];
        int4 xb4 = *(const int4*)&sxw[8 * lq + 4];
        STEP(xa.x); STEP(xa.y); STEP(xa.z); STEP(xa.w);
        STEP(xb4.x); STEP(xb4.y); STEP(xb4.z); STEP(xb4.w);
        // rescale by segment max
        float m = fmaxf(fmaxf(lo2(FM01), hi2(FM01)), fmaxf(lo2(FM23), hi2(FM23)));
        m = fmaxf(m, fmaxf(fmaxf(lo2(FI01), hi2(FI01)), fmaxf(lo2(FI23), hi2(FI23))));
        m = fmaxf(m, fmaxf(FM64, FI64));
        #pragma unroll
        for (int off = 1; off < 16; off <<= 1)
            m = fmaxf(m, __shfl_xor_sync(FULL, m, off, 16));
        m = fmaxf(m, 1e-30f);
        float r = 1.0f / m;
        S += __logf(m);
        u64 rr = pk(r, r);
        FM01 = mul2(FM01, rr); FM23 = mul2(FM23, rr);
        FI01 = mul2(FI01, rr); FI23 = mul2(FI23, rr);
        w01 = mul2(w01, rr);   w23 = mul2(w23, rr);
        PRE01 = mul2(PRE01, rr); PRE23 = mul2(PRE23, rr);  // linear in states
        FM64 *= r; FI64 *= r; incl *= r;
    }

    // ---- final: three end transitions (sl=15 holds state 64 & full prefix) ----
    float fdTop = P_B * incl;
    float Pfin = fmaf(t64D2M, fdTop, fmaf(t64I2M, FI64, t64M2M * FM64));
    float loss = -(S + __logf(Pfin));             // valid on sl=15

    // ---- KLD: 16 segment lanes, one latent dim each ----
    float kt;
    {
        float mu = mus[b * 16 + sl];
        float lv = logvars[b * 16 + sl];
        kt = 1.0f + lv - mu * mu - __expf(lv);
    }
    #pragma unroll
    for (int off = 1; off < 16; off <<= 1)
        kt += __shfl_xor_sync(FULL, kt, off, 16);

    if (sl == 15) sred[warp * 2 + seg] = loss - 0.5f * kt;
    __syncthreads();
    if (threadIdx.x == 0) {
        float v = ((sred[0] + sred[1]) + (sred[2] + sred[3]))
                + ((sred[4] + sred[5]) + (sred[6] + sred[7]));
        g_partials[blockIdx.x] = v;
        __threadfence();
        unsigned t = atomicAdd(&g_cnt, 1u);
        sflag = (t == gridDim.x - 1) ? 1 : 0;
    }
    __syncthreads();
    if (sflag) {
        float s = 0.0f;
        #pragma unroll
        for (int i = 0; i < 4; i++)
            s += __ldcg(&g_partials[threadIdx.x + 128 * i]);
        s2[threadIdx.x] = s;
        __syncthreads();
        #pragma unroll
        for (int st = 64; st; st >>= 1) {
            if (threadIdx.x < st) s2[threadIdx.x] += s2[threadIdx.x + st];
            __syncthreads();
        }
        if (threadIdx.x == 0) {
            out[0] = s2[0] * (1.0f / 4096.0f);
            g_cnt = 0;  // self-reset for graph replay
        }
    }
#undef STEP
#undef DCHAIN
}

extern "C" void kernel_launch(void* const* d_in, const int* in_sizes, int n_in,
                              void* d_out, int out_size) {
    const int*   x  = (const int*)d_in[0];    // batch_input (B,128)
    const float* a  = (const float*)d_in[1];  // transition_probs (B,65,7)
    const float* e  = (const float*)d_in[2];  // emission_probs (B,64,4)
    const float* mu = (const float*)d_in[3];  // mus (B,16)
    const float* lv = (const float*)d_in[4];  // logvars (B,16)
    const int B = in_sizes[0] / 128;          // 4096
    phmm_kernel<<<B / 8, 128>>>(x, a, e, mu, lv, (float*)d_out);
}